// round 1
// baseline (speedup 1.0000x reference)
#include <cuda_runtime.h>
#include <math.h>

// Problem constants
#define S_LEN   2048
#define BATCH   8
#define DIM     512
#define HID     512
#define N3      1536                  // 3*HID
#define MROWS   (S_LEN * BATCH)       // 16384
#define NODES   7
#define NCHUNK  32
#define CHLEN   (S_LEN / NCHUNK)      // 64
#define LANES   (BATCH * HID)         // 4096

// Scratch (static __device__ arrays: allocation-free, graph-safe)
__device__ float g_V[(size_t)NODES * MROWS * N3];      // per-node V = X @ W_proj  (~704 MB)
__device__ float g_H[(size_t)6 * MROWS * HID];         // Hout of nodes 1..6 (slot = node-1)
__device__ float g_T[(size_t)NODES * MROWS * 2];       // t = sigmoid(X @ W_T + b_T)
__device__ float g_A  [(size_t)NODES * NCHUNK * LANES];
__device__ float g_Bc [(size_t)NODES * NCHUNK * LANES];
__device__ float g_Cin[(size_t)NODES * NCHUNK * LANES];
__device__ float g_CM [(size_t)NCHUNK * LANES];        // per-chunk maxima for node 0

__device__ __forceinline__ float sigmoidf(float x) {
    return 1.0f / (1.0f + expf(-x));
}

// ---------------------------------------------------------------------------
// GEMM: V[node] = X @ W_proj[node], M=16384, N=1536, K=512, fp32 SIMT,
// 128x128 block tile, K-step 8, double-buffered smem, 8x8 per thread.
// ---------------------------------------------------------------------------
__global__ __launch_bounds__(256) void gemm3_kernel(const float* __restrict__ X,
                                                    const float* __restrict__ Wp) {
    const int node = blockIdx.z;
    const int n0 = blockIdx.x * 128;
    const int m0 = blockIdx.y * 128;
    const float* Bg = Wp + (size_t)node * DIM * N3;
    float* C = g_V + (size_t)node * MROWS * N3;

    __shared__ float As[2][8][128];
    __shared__ float Bs[2][8][128];

    const int tid = threadIdx.x;
    const int a_row = tid >> 1;          // 0..127
    const int a_k   = (tid & 1) * 4;     // 0 or 4
    const int b_k   = tid >> 5;          // 0..7
    const int b_col = (tid & 31) * 4;    // 0..124

    const float* Aptr = X  + (size_t)(m0 + a_row) * DIM + a_k;
    const float* Bptr = Bg + (size_t)b_k * N3 + n0 + b_col;

    // preload tile 0
    {
        float4 av = *(const float4*)(Aptr);
        float4 bv = *(const float4*)(Bptr);
        As[0][a_k + 0][a_row] = av.x;
        As[0][a_k + 1][a_row] = av.y;
        As[0][a_k + 2][a_row] = av.z;
        As[0][a_k + 3][a_row] = av.w;
        *(float4*)&Bs[0][b_k][b_col] = bv;
    }
    __syncthreads();

    const int ty = tid >> 4;   // 0..15
    const int tx = tid & 15;   // 0..15

    float acc[8][8];
    #pragma unroll
    for (int i = 0; i < 8; i++)
        #pragma unroll
        for (int j = 0; j < 8; j++) acc[i][j] = 0.0f;

    int buf = 0;
    for (int k0 = 8; k0 <= DIM; k0 += 8) {
        float4 an, bn;
        const bool more = (k0 < DIM);
        if (more) {
            an = *(const float4*)(Aptr + k0);
            bn = *(const float4*)(Bptr + (size_t)k0 * N3);
        }
        #pragma unroll
        for (int kk = 0; kk < 8; kk++) {
            float4 a0 = *(const float4*)&As[buf][kk][ty * 4];
            float4 a1 = *(const float4*)&As[buf][kk][64 + ty * 4];
            float4 b0 = *(const float4*)&Bs[buf][kk][tx * 4];
            float4 b1 = *(const float4*)&Bs[buf][kk][64 + tx * 4];
            float a[8] = {a0.x, a0.y, a0.z, a0.w, a1.x, a1.y, a1.z, a1.w};
            float b[8] = {b0.x, b0.y, b0.z, b0.w, b1.x, b1.y, b1.z, b1.w};
            #pragma unroll
            for (int i = 0; i < 8; i++)
                #pragma unroll
                for (int j = 0; j < 8; j++)
                    acc[i][j] = fmaf(a[i], b[j], acc[i][j]);
        }
        if (more) {
            const int nb = buf ^ 1;
            As[nb][a_k + 0][a_row] = an.x;
            As[nb][a_k + 1][a_row] = an.y;
            As[nb][a_k + 2][a_row] = an.z;
            As[nb][a_k + 3][a_row] = an.w;
            *(float4*)&Bs[nb][b_k][b_col] = bn;
            __syncthreads();
            buf = nb;
        }
    }

    #pragma unroll
    for (int i = 0; i < 8; i++) {
        const int r = m0 + ((i < 4) ? (ty * 4 + i) : (64 + ty * 4 + (i - 4)));
        float* cr = C + (size_t)r * N3 + n0;
        *(float4*)&cr[tx * 4]      = make_float4(acc[i][0], acc[i][1], acc[i][2], acc[i][3]);
        *(float4*)&cr[64 + tx * 4] = make_float4(acc[i][4], acc[i][5], acc[i][6], acc[i][7]);
    }
}

// ---------------------------------------------------------------------------
// T projection: g_T[node][m][0:2] = sigmoid(X[m,:] @ W_T[node] + b_T[node])
// one warp per (node, row)
// ---------------------------------------------------------------------------
__global__ __launch_bounds__(256) void tproj_kernel(const float* __restrict__ X,
                                                    const float* __restrict__ WT,
                                                    const float* __restrict__ bT) {
    const int gw = (blockIdx.x * blockDim.x + threadIdx.x) >> 5;
    const int lane = threadIdx.x & 31;
    if (gw >= NODES * MROWS) return;
    const int node = gw >> 14;            // / 16384
    const int m = gw & (MROWS - 1);
    const float* xr = X + (size_t)m * DIM;
    const float* w = WT + (size_t)node * DIM * 2;
    float s0 = 0.0f, s1 = 0.0f;
    #pragma unroll 4
    for (int k = lane; k < DIM; k += 32) {
        const float x = xr[k];
        const float2 wv = *(const float2*)&w[k * 2];
        s0 = fmaf(x, wv.x, s0);
        s1 = fmaf(x, wv.y, s1);
    }
    #pragma unroll
    for (int o = 16; o > 0; o >>= 1) {
        s0 += __shfl_down_sync(0xFFFFFFFFu, s0, o);
        s1 += __shfl_down_sync(0xFFFFFFFFu, s1, o);
    }
    if (lane == 0) {
        s0 += bT[node * 2 + 0];
        s1 += bT[node * 2 + 1];
        const size_t t = ((size_t)node * MROWS + m) * 2;
        g_T[t + 0] = sigmoidf(s0);
        g_T[t + 1] = sigmoidf(s1);
    }
}

// ---------------------------------------------------------------------------
// Chunked scan, pass A: per (node, chunk, lane) compute affine summary (A, B)
// for c_t = f z + (1-f) c  => c = A*c_in + B over the chunk.
// ---------------------------------------------------------------------------
template<bool INTERNAL>
__global__ __launch_bounds__(128) void scanA_kernel(int first_node) {
    const int node  = first_node + blockIdx.z;
    const int chunk = blockIdx.y;
    const int lane  = blockIdx.x * 128 + threadIdx.x;  // 0..4095
    const int b = lane >> 9;
    const int h = lane & 511;

    const float* Vn = g_V + (size_t)node * MROWS * N3;
    const float* Tn = g_T + (size_t)node * MROWS * 2;
    const float* HF = g_H + (size_t)(2 * node) * MROWS * HID;     // child1 = 2*node+1 -> slot 2*node

    float A = 1.0f, Bc = 0.0f;
    const int s0 = chunk * CHLEN;
    #pragma unroll 4
    for (int si = 0; si < CHLEN; si++) {
        const int m = (s0 + si) * BATCH + b;
        const size_t vi = (size_t)m * N3 + h;
        float z = __ldg(Vn + vi);
        float f = __ldg(Vn + vi + HID);
        if (INTERNAL) {
            const float t1 = __ldg(Tn + (size_t)m * 2);
            const float hF = __ldg(HF + (size_t)m * HID + h);
            f = hF * t1 + (1.0f - t1) * f;
        }
        z = fmaxf(z, 0.0f);
        f = sigmoidf(f);
        const float a = 1.0f - f;
        A *= a;
        Bc = fmaf(a, Bc, f * z);
    }
    const size_t idx = ((size_t)node * NCHUNK + chunk) * LANES + lane;
    g_A[idx] = A;
    g_Bc[idx] = Bc;
}

// Pass mid: per lane, sequentially compose 32 chunk summaries -> c_in per chunk
__global__ __launch_bounds__(128) void scanMid_kernel(int first_node) {
    const int node = first_node + blockIdx.y;
    const int lane = blockIdx.x * 128 + threadIdx.x;
    float c = 0.0f;
    #pragma unroll
    for (int j = 0; j < NCHUNK; j++) {
        const size_t idx = ((size_t)node * NCHUNK + j) * LANES + lane;
        g_Cin[idx] = c;
        c = fmaf(g_A[idx], c, g_Bc[idx]);
    }
}

// Pass B: recompute, run the chunk from c_in, write Hout (+X residual),
// track per-chunk max of pre-residual Hout for the root node.
template<bool INTERNAL, bool ROOT>
__global__ __launch_bounds__(128) void scanB_kernel(int first_node,
                                                    const float* __restrict__ X,
                                                    float* __restrict__ out) {
    const int node  = first_node + blockIdx.z;
    const int chunk = blockIdx.y;
    const int lane  = blockIdx.x * 128 + threadIdx.x;
    const int b = lane >> 9;
    const int h = lane & 511;

    const float* Vn = g_V + (size_t)node * MROWS * N3;
    const float* Tn = g_T + (size_t)node * MROWS * 2;
    const float* HF = g_H + (size_t)(2 * node) * MROWS * HID;       // child F (node 2i+1)
    const float* HO = g_H + (size_t)(2 * node + 1) * MROWS * HID;   // child O (node 2i+2)
    float* hout = ROOT ? out : (g_H + (size_t)(node - 1) * MROWS * HID);

    float c = g_Cin[((size_t)node * NCHUNK + chunk) * LANES + lane];
    float cm = -3.4e38f;
    const int s0 = chunk * CHLEN;
    #pragma unroll 4
    for (int si = 0; si < CHLEN; si++) {
        const int m = (s0 + si) * BATCH + b;
        const size_t vi = (size_t)m * N3 + h;
        float z = __ldg(Vn + vi);
        float f = __ldg(Vn + vi + HID);
        float o = __ldg(Vn + vi + 2 * HID);
        if (INTERNAL) {
            const float2 t = *(const float2*)(Tn + (size_t)m * 2);
            const float hF = __ldg(HF + (size_t)m * HID + h);
            const float hO = __ldg(HO + (size_t)m * HID + h);
            f = hF * t.x + (1.0f - t.x) * f;
            o = hO * t.y + (1.0f - t.y) * o;
        }
        z = fmaxf(z, 0.0f);
        f = sigmoidf(f);
        c = fmaf(f, z, (1.0f - f) * c);
        const float ho = c * sigmoidf(o);
        if (ROOT) cm = fmaxf(cm, ho);
        hout[(size_t)m * HID + h] = ho + __ldg(X + (size_t)m * DIM + h);
    }
    if (ROOT) g_CM[(size_t)chunk * LANES + lane] = cm;
}

// Final Cmax reduction over chunks (root node only)
__global__ __launch_bounds__(128) void cmax_kernel(float* __restrict__ cmax_out) {
    const int lane = blockIdx.x * 128 + threadIdx.x;  // 0..4095
    float cm = -3.4e38f;
    #pragma unroll
    for (int j = 0; j < NCHUNK; j++)
        cm = fmaxf(cm, g_CM[(size_t)j * LANES + lane]);
    cmax_out[lane] = cm;
}

// ---------------------------------------------------------------------------
extern "C" void kernel_launch(void* const* d_in, const int* in_sizes, int n_in,
                              void* d_out, int out_size) {
    const float* X  = (const float*)d_in[0];
    const float* Wp = (const float*)d_in[1];
    const float* WT = (const float*)d_in[2];
    const float* bT = (const float*)d_in[3];
    float* out = (float*)d_out;
    (void)in_sizes; (void)n_in;

    // Phase 1: all node projections (only depend on X)
    gemm3_kernel<<<dim3(N3 / 128, MROWS / 128, NODES), 256>>>(X, Wp);
    tproj_kernel<<<(NODES * MROWS * 32 + 255) / 256, 256>>>(X, WT, bT);

    const dim3 blk(128);
    // Level 3: leaves 3..6 (no merge)
    {
        dim3 g(LANES / 128, NCHUNK, 4);
        scanA_kernel<false><<<g, blk>>>(3);
        scanMid_kernel<<<dim3(LANES / 128, 4), blk>>>(3);
        scanB_kernel<false, false><<<g, blk>>>(3, X, out);
    }
    // Level 2: nodes 1,2 (merge children 3/4 and 5/6)
    {
        dim3 g(LANES / 128, NCHUNK, 2);
        scanA_kernel<true><<<g, blk>>>(1);
        scanMid_kernel<<<dim3(LANES / 128, 2), blk>>>(1);
        scanB_kernel<true, false><<<g, blk>>>(1, X, out);
    }
    // Level 1: root node 0 (merge children 1/2), write Hout to d_out
    {
        dim3 g(LANES / 128, NCHUNK, 1);
        scanA_kernel<true><<<g, blk>>>(0);
        scanMid_kernel<<<dim3(LANES / 128, 1), blk>>>(0);
        scanB_kernel<true, true><<<g, blk>>>(0, X, out);
    }
    // Cmax (second output), if the output buffer includes it
    if (out_size >= MROWS * HID + LANES)
        cmax_kernel<<<LANES / 128, blk>>>(out + (size_t)MROWS * HID);
}

// round 3
// speedup vs baseline: 1.9339x; 1.9339x over previous
#include <cuda_runtime.h>
#include <math.h>
#include <stdint.h>

// Problem constants
#define S_LEN   2048
#define BATCH   8
#define DIM     512
#define HID     512
#define N3      1536                  // 3*HID
#define MROWS   (S_LEN * BATCH)       // 16384
#define NODES   7
#define NCHUNK  32
#define CHLEN   (S_LEN / NCHUNK)      // 64
#define LANES   (BATCH * HID)         // 4096

// Scratch (static __device__ arrays: allocation-free, graph-safe)
__device__ __align__(256) float g_V[(size_t)NODES * MROWS * N3];   // per-node V = X @ W_proj
__device__ __align__(256) float g_H[(size_t)6 * MROWS * HID];      // Hout of nodes 1..6
__device__ __align__(256) float g_T[(size_t)NODES * MROWS * 2];
__device__ __align__(256) float g_A  [(size_t)NODES * NCHUNK * LANES];
__device__ __align__(256) float g_Bc [(size_t)NODES * NCHUNK * LANES];
__device__ __align__(256) float g_Cin[(size_t)NODES * NCHUNK * LANES];
__device__ __align__(256) float g_CM [(size_t)NCHUNK * LANES];

__device__ __forceinline__ float sigmoidf(float x) {
    return 1.0f / (1.0f + expf(-x));
}

// tf32 conversion: destination must be a b32 register in PTX
__device__ __forceinline__ float to_tf32(float x) {
    uint32_t r;
    asm("cvt.rna.tf32.f32 %0, %1;\n" : "=r"(r) : "f"(x));
    return __uint_as_float(r);
}

__device__ __forceinline__ void mma_tf32(float* c, const uint32_t* a, const uint32_t* b) {
    asm volatile(
        "mma.sync.aligned.m16n8k8.row.col.f32.tf32.tf32.f32 "
        "{%0,%1,%2,%3}, {%4,%5,%6,%7}, {%8,%9}, {%0,%1,%2,%3};\n"
        : "+f"(c[0]), "+f"(c[1]), "+f"(c[2]), "+f"(c[3])
        : "r"(a[0]), "r"(a[1]), "r"(a[2]), "r"(a[3]), "r"(b[0]), "r"(b[1]));
}

// ---------------------------------------------------------------------------
// Tensor-core GEMM: V[node] = X @ W_proj[node], M=16384, N=1536, K=512.
// tf32 mma.sync, 128x128x16 block tile, 8 warps x (64x32), double buffered.
// ---------------------------------------------------------------------------
__global__ __launch_bounds__(256) void gemm_tf32_kernel(const float* __restrict__ X,
                                                        const float* __restrict__ Wp) {
    const int node = blockIdx.z;
    const int n0 = blockIdx.x * 128;
    const int m0 = blockIdx.y * 128;
    const float* Ag = X + (size_t)m0 * DIM;
    const float* Bg = Wp + (size_t)node * DIM * N3 + n0;
    float* C = g_V + (size_t)node * MROWS * N3;

    __shared__ float As[2][16][136];   // [k][m], stride 136 => conflict-free frag loads
    __shared__ float Bs[2][16][136];   // [k][n]

    const int tid = threadIdx.x;
    // global->smem staging indices
    const int ar = tid >> 2;           // 0..63 (+64)
    const int ak = (tid & 3) * 4;      // 0,4,8,12
    const int bk = tid >> 5;           // 0..7 (+8)
    const int bn = (tid & 31) * 4;     // 0..124
    // warp / fragment indices
    const int w = tid >> 5;
    const int lane = tid & 31;
    const int gid = lane >> 2;         // 0..7
    const int tig = lane & 3;          // 0..3
    const int wm = (w & 1) * 64;
    const int wn = (w >> 1) * 32;

    float acc[4][4][4];
    #pragma unroll
    for (int mi = 0; mi < 4; mi++)
        #pragma unroll
        for (int ni = 0; ni < 4; ni++)
            #pragma unroll
            for (int c = 0; c < 4; c++) acc[mi][ni][c] = 0.0f;

    // preload tile 0
    {
        float4 a0 = *(const float4*)(Ag + (size_t)ar * DIM + ak);
        float4 a1 = *(const float4*)(Ag + (size_t)(ar + 64) * DIM + ak);
        float4 b0 = *(const float4*)(Bg + (size_t)bk * N3 + bn);
        float4 b1 = *(const float4*)(Bg + (size_t)(bk + 8) * N3 + bn);
        As[0][ak + 0][ar] = to_tf32(a0.x); As[0][ak + 1][ar] = to_tf32(a0.y);
        As[0][ak + 2][ar] = to_tf32(a0.z); As[0][ak + 3][ar] = to_tf32(a0.w);
        As[0][ak + 0][ar + 64] = to_tf32(a1.x); As[0][ak + 1][ar + 64] = to_tf32(a1.y);
        As[0][ak + 2][ar + 64] = to_tf32(a1.z); As[0][ak + 3][ar + 64] = to_tf32(a1.w);
        float4 cb0 = make_float4(to_tf32(b0.x), to_tf32(b0.y), to_tf32(b0.z), to_tf32(b0.w));
        float4 cb1 = make_float4(to_tf32(b1.x), to_tf32(b1.y), to_tf32(b1.z), to_tf32(b1.w));
        *(float4*)&Bs[0][bk][bn] = cb0;
        *(float4*)&Bs[0][bk + 8][bn] = cb1;
    }
    __syncthreads();

    int buf = 0;
    #pragma unroll 1
    for (int kt = 0; kt < 32; kt++) {
        float4 na0, na1, nb0, nb1;
        const bool more = (kt < 31);
        if (more) {
            const int k0 = (kt + 1) * 16;
            na0 = *(const float4*)(Ag + (size_t)ar * DIM + k0 + ak);
            na1 = *(const float4*)(Ag + (size_t)(ar + 64) * DIM + k0 + ak);
            nb0 = *(const float4*)(Bg + (size_t)(k0 + bk) * N3 + bn);
            nb1 = *(const float4*)(Bg + (size_t)(k0 + bk + 8) * N3 + bn);
        }

        #pragma unroll
        for (int kk = 0; kk < 16; kk += 8) {
            uint32_t a[4][4], b[4][2];
            #pragma unroll
            for (int mi = 0; mi < 4; mi++) {
                const int m = wm + mi * 16 + gid;
                a[mi][0] = __float_as_uint(As[buf][kk + tig][m]);
                a[mi][1] = __float_as_uint(As[buf][kk + tig][m + 8]);
                a[mi][2] = __float_as_uint(As[buf][kk + tig + 4][m]);
                a[mi][3] = __float_as_uint(As[buf][kk + tig + 4][m + 8]);
            }
            #pragma unroll
            for (int ni = 0; ni < 4; ni++) {
                const int n = wn + ni * 8 + gid;
                b[ni][0] = __float_as_uint(Bs[buf][kk + tig][n]);
                b[ni][1] = __float_as_uint(Bs[buf][kk + tig + 4][n]);
            }
            #pragma unroll
            for (int mi = 0; mi < 4; mi++)
                #pragma unroll
                for (int ni = 0; ni < 4; ni++)
                    mma_tf32(acc[mi][ni], a[mi], b[ni]);
        }

        if (more) {
            const int nb = buf ^ 1;
            As[nb][ak + 0][ar] = to_tf32(na0.x); As[nb][ak + 1][ar] = to_tf32(na0.y);
            As[nb][ak + 2][ar] = to_tf32(na0.z); As[nb][ak + 3][ar] = to_tf32(na0.w);
            As[nb][ak + 0][ar + 64] = to_tf32(na1.x); As[nb][ak + 1][ar + 64] = to_tf32(na1.y);
            As[nb][ak + 2][ar + 64] = to_tf32(na1.z); As[nb][ak + 3][ar + 64] = to_tf32(na1.w);
            float4 cb0 = make_float4(to_tf32(nb0.x), to_tf32(nb0.y), to_tf32(nb0.z), to_tf32(nb0.w));
            float4 cb1 = make_float4(to_tf32(nb1.x), to_tf32(nb1.y), to_tf32(nb1.z), to_tf32(nb1.w));
            *(float4*)&Bs[nb][bk][bn] = cb0;
            *(float4*)&Bs[nb][bk + 8][bn] = cb1;
        }
        __syncthreads();
        buf ^= 1;
    }

    // epilogue: float2 stores, 4 threads (tig 0..3) cover 32 contiguous bytes
    #pragma unroll
    for (int mi = 0; mi < 4; mi++) {
        #pragma unroll
        for (int ni = 0; ni < 4; ni++) {
            const int row = m0 + wm + mi * 16 + gid;
            const int col = n0 + wn + ni * 8 + tig * 2;
            *(float2*)&C[(size_t)row * N3 + col] =
                make_float2(acc[mi][ni][0], acc[mi][ni][1]);
            *(float2*)&C[(size_t)(row + 8) * N3 + col] =
                make_float2(acc[mi][ni][2], acc[mi][ni][3]);
        }
    }
}

// ---------------------------------------------------------------------------
// T projection: g_T[node][m][0:2] = sigmoid(X[m,:] @ W_T[node] + b_T[node])
// ---------------------------------------------------------------------------
__global__ __launch_bounds__(256) void tproj_kernel(const float* __restrict__ X,
                                                    const float* __restrict__ WT,
                                                    const float* __restrict__ bT) {
    const int gw = (blockIdx.x * blockDim.x + threadIdx.x) >> 5;
    const int lane = threadIdx.x & 31;
    if (gw >= NODES * MROWS) return;
    const int node = gw >> 14;
    const int m = gw & (MROWS - 1);
    const float* xr = X + (size_t)m * DIM;
    const float* w = WT + (size_t)node * DIM * 2;
    float s0 = 0.0f, s1 = 0.0f;
    #pragma unroll 4
    for (int k = lane; k < DIM; k += 32) {
        const float x = xr[k];
        const float2 wv = *(const float2*)&w[k * 2];
        s0 = fmaf(x, wv.x, s0);
        s1 = fmaf(x, wv.y, s1);
    }
    #pragma unroll
    for (int o = 16; o > 0; o >>= 1) {
        s0 += __shfl_down_sync(0xFFFFFFFFu, s0, o);
        s1 += __shfl_down_sync(0xFFFFFFFFu, s1, o);
    }
    if (lane == 0) {
        s0 += bT[node * 2 + 0];
        s1 += bT[node * 2 + 1];
        const size_t t = ((size_t)node * MROWS + m) * 2;
        g_T[t + 0] = sigmoidf(s0);
        g_T[t + 1] = sigmoidf(s1);
    }
}

// ---------------------------------------------------------------------------
// Chunked scan, pass A: per (node, chunk, lane) affine summary (A, B)
// ---------------------------------------------------------------------------
template<bool INTERNAL>
__global__ __launch_bounds__(128) void scanA_kernel(int first_node) {
    const int node  = first_node + blockIdx.z;
    const int chunk = blockIdx.y;
    const int lane  = blockIdx.x * 128 + threadIdx.x;
    const int b = lane >> 9;
    const int h = lane & 511;

    const float* Vn = g_V + (size_t)node * MROWS * N3;
    const float* Tn = g_T + (size_t)node * MROWS * 2;
    const float* HF = g_H + (size_t)(2 * node) * MROWS * HID;

    float A = 1.0f, Bc = 0.0f;
    const int s0 = chunk * CHLEN;
    #pragma unroll 4
    for (int si = 0; si < CHLEN; si++) {
        const int m = (s0 + si) * BATCH + b;
        const size_t vi = (size_t)m * N3 + h;
        float z = __ldg(Vn + vi);
        float f = __ldg(Vn + vi + HID);
        if (INTERNAL) {
            const float t1 = __ldg(Tn + (size_t)m * 2);
            const float hF = __ldg(HF + (size_t)m * HID + h);
            f = hF * t1 + (1.0f - t1) * f;
        }
        z = fmaxf(z, 0.0f);
        f = sigmoidf(f);
        const float a = 1.0f - f;
        A *= a;
        Bc = fmaf(a, Bc, f * z);
    }
    const size_t idx = ((size_t)node * NCHUNK + chunk) * LANES + lane;
    g_A[idx] = A;
    g_Bc[idx] = Bc;
}

__global__ __launch_bounds__(128) void scanMid_kernel(int first_node) {
    const int node = first_node + blockIdx.y;
    const int lane = blockIdx.x * 128 + threadIdx.x;
    float c = 0.0f;
    #pragma unroll
    for (int j = 0; j < NCHUNK; j++) {
        const size_t idx = ((size_t)node * NCHUNK + j) * LANES + lane;
        g_Cin[idx] = c;
        c = fmaf(g_A[idx], c, g_Bc[idx]);
    }
}

template<bool INTERNAL, bool ROOT>
__global__ __launch_bounds__(128) void scanB_kernel(int first_node,
                                                    const float* __restrict__ X,
                                                    float* __restrict__ out) {
    const int node  = first_node + blockIdx.z;
    const int chunk = blockIdx.y;
    const int lane  = blockIdx.x * 128 + threadIdx.x;
    const int b = lane >> 9;
    const int h = lane & 511;

    const float* Vn = g_V + (size_t)node * MROWS * N3;
    const float* Tn = g_T + (size_t)node * MROWS * 2;
    const float* HF = g_H + (size_t)(2 * node) * MROWS * HID;
    const float* HO = g_H + (size_t)(2 * node + 1) * MROWS * HID;
    float* hout = ROOT ? out : (g_H + (size_t)(node - 1) * MROWS * HID);

    float c = g_Cin[((size_t)node * NCHUNK + chunk) * LANES + lane];
    float cm = -3.4e38f;
    const int s0 = chunk * CHLEN;
    #pragma unroll 4
    for (int si = 0; si < CHLEN; si++) {
        const int m = (s0 + si) * BATCH + b;
        const size_t vi = (size_t)m * N3 + h;
        float z = __ldg(Vn + vi);
        float f = __ldg(Vn + vi + HID);
        float o = __ldg(Vn + vi + 2 * HID);
        if (INTERNAL) {
            const float2 t = *(const float2*)(Tn + (size_t)m * 2);
            const float hF = __ldg(HF + (size_t)m * HID + h);
            const float hO = __ldg(HO + (size_t)m * HID + h);
            f = hF * t.x + (1.0f - t.x) * f;
            o = hO * t.y + (1.0f - t.y) * o;
        }
        z = fmaxf(z, 0.0f);
        f = sigmoidf(f);
        c = fmaf(f, z, (1.0f - f) * c);
        const float ho = c * sigmoidf(o);
        if (ROOT) cm = fmaxf(cm, ho);
        hout[(size_t)m * HID + h] = ho + __ldg(X + (size_t)m * DIM + h);
    }
    if (ROOT) g_CM[(size_t)chunk * LANES + lane] = cm;
}

__global__ __launch_bounds__(128) void cmax_kernel(float* __restrict__ cmax_out) {
    const int lane = blockIdx.x * 128 + threadIdx.x;
    float cm = -3.4e38f;
    #pragma unroll
    for (int j = 0; j < NCHUNK; j++)
        cm = fmaxf(cm, g_CM[(size_t)j * LANES + lane]);
    cmax_out[lane] = cm;
}

// ---------------------------------------------------------------------------
extern "C" void kernel_launch(void* const* d_in, const int* in_sizes, int n_in,
                              void* d_out, int out_size) {
    const float* X  = (const float*)d_in[0];
    const float* Wp = (const float*)d_in[1];
    const float* WT = (const float*)d_in[2];
    const float* bT = (const float*)d_in[3];
    float* out = (float*)d_out;
    (void)in_sizes; (void)n_in;

    gemm_tf32_kernel<<<dim3(N3 / 128, MROWS / 128, NODES), 256>>>(X, Wp);
    tproj_kernel<<<(NODES * MROWS * 32 + 255) / 256, 256>>>(X, WT, bT);

    const dim3 blk(128);
    {   // leaves 3..6
        dim3 g(LANES / 128, NCHUNK, 4);
        scanA_kernel<false><<<g, blk>>>(3);
        scanMid_kernel<<<dim3(LANES / 128, 4), blk>>>(3);
        scanB_kernel<false, false><<<g, blk>>>(3, X, out);
    }
    {   // nodes 1,2
        dim3 g(LANES / 128, NCHUNK, 2);
        scanA_kernel<true><<<g, blk>>>(1);
        scanMid_kernel<<<dim3(LANES / 128, 2), blk>>>(1);
        scanB_kernel<true, false><<<g, blk>>>(1, X, out);
    }
    {   // root node 0
        dim3 g(LANES / 128, NCHUNK, 1);
        scanA_kernel<true><<<g, blk>>>(0);
        scanMid_kernel<<<dim3(LANES / 128, 1), blk>>>(0);
        scanB_kernel<true, true><<<g, blk>>>(0, X, out);
    }
    if (out_size >= MROWS * HID + LANES)
        cmax_kernel<<<LANES / 128, blk>>>(out + (size_t)MROWS * HID);
}

// round 4
// speedup vs baseline: 1.9594x; 1.0132x over previous
#include <cuda_runtime.h>
#include <math.h>
#include <stdint.h>

// Problem constants
#define S_LEN   2048
#define BATCH   8
#define DIM     512
#define HID     512
#define N3      1536                  // 3*HID
#define MROWS   (S_LEN * BATCH)       // 16384
#define NODES   7
#define NCHUNK  32
#define CHLEN   (S_LEN / NCHUNK)      // 64
#define LANES   (BATCH * HID)         // 4096

// GEMM tiling
#define BM 128
#define BN 128
#define BK 16
#define APITCH 20      // A smem pitch (words): (gid*20+tig) distinct mod 32
#define BPITCH 136     // B smem pitch (words): (tig*8+gid) distinct mod 32

// Scratch (static __device__ arrays: allocation-free, graph-safe)
__device__ __align__(256) float g_V[(size_t)NODES * MROWS * N3];
__device__ __align__(256) float g_H[(size_t)6 * MROWS * HID];
__device__ __align__(256) float g_T[(size_t)NODES * MROWS * 2];
__device__ __align__(256) float g_A  [(size_t)NODES * NCHUNK * LANES];
__device__ __align__(256) float g_Bc [(size_t)NODES * NCHUNK * LANES];
__device__ __align__(256) float g_Cin[(size_t)NODES * NCHUNK * LANES];
__device__ __align__(256) float g_CM [(size_t)NCHUNK * LANES];

__device__ __forceinline__ float sigmoidf(float x) {
    return 1.0f / (1.0f + expf(-x));
}

__device__ __forceinline__ uint32_t smem_u32(const void* p) {
    return (uint32_t)__cvta_generic_to_shared(p);
}

__device__ __forceinline__ void cp_async16(uint32_t dst, const void* src) {
    asm volatile("cp.async.cg.shared.global [%0], [%1], 16;\n" :: "r"(dst), "l"(src));
}

__device__ __forceinline__ void cp_commit() {
    asm volatile("cp.async.commit_group;\n");
}

template<int N>
__device__ __forceinline__ void cp_wait() {
    asm volatile("cp.async.wait_group %0;\n" :: "n"(N));
}

__device__ __forceinline__ void mma_tf32(float* c, const uint32_t* a, const uint32_t* b) {
    asm volatile(
        "mma.sync.aligned.m16n8k8.row.col.f32.tf32.tf32.f32 "
        "{%0,%1,%2,%3}, {%4,%5,%6,%7}, {%8,%9}, {%0,%1,%2,%3};\n"
        : "+f"(c[0]), "+f"(c[1]), "+f"(c[2]), "+f"(c[3])
        : "r"(a[0]), "r"(a[1]), "r"(a[2]), "r"(a[3]), "r"(b[0]), "r"(b[1]));
}

// ---------------------------------------------------------------------------
// Tensor-core GEMM: V[node] = X @ W_proj[node]. 128x128x16 tiles, 4 warps of
// 64x64, cp.async double-buffer, raw f32 -> tf32 HW truncation (no cvt).
// ---------------------------------------------------------------------------
__global__ __launch_bounds__(128) void gemm_tf32_kernel(const float* __restrict__ X,
                                                        const float* __restrict__ Wp) {
    __shared__ float sA[2][BM * APITCH];   // [m][k], pitch 20
    __shared__ float sB[2][BK * BPITCH];   // [k][n], pitch 136

    const int node = blockIdx.z;
    const int n0 = blockIdx.x * BN;
    const int m0 = blockIdx.y * BM;
    const float* Ag = X + (size_t)m0 * DIM;
    const float* Bg = Wp + (size_t)node * DIM * N3 + n0;
    float* C = g_V + (size_t)node * MROWS * N3;

    const int tid = threadIdx.x;
    const int w = tid >> 5;
    const int lane = tid & 31;
    const int gid = lane >> 2;   // 0..7
    const int tig = lane & 3;    // 0..3
    const int wm = (w >> 1) * 64;
    const int wn = (w & 1) * 64;

    const uint32_t sAu0 = smem_u32(&sA[0][0]);
    const uint32_t sBu0 = smem_u32(&sB[0][0]);

    float acc[4][8][4];
    #pragma unroll
    for (int mi = 0; mi < 4; mi++)
        #pragma unroll
        for (int ni = 0; ni < 8; ni++)
            #pragma unroll
            for (int c = 0; c < 4; c++) acc[mi][ni][c] = 0.0f;

    // B staging indices for this thread (4 chunks)
    // cid = i*128 + tid: kb = cid>>5, nc = cid&31

    // prefetch ktile 0 into stage 0
    {
        const uint32_t dA = sAu0 + (uint32_t)(tid * APITCH) * 4u;
        const float* srcA = Ag + (size_t)tid * DIM;
        #pragma unroll
        for (int kc = 0; kc < 4; kc++) cp_async16(dA + kc * 16u, srcA + kc * 4);
        #pragma unroll
        for (int i = 0; i < 4; i++) {
            const int cid = i * 128 + tid;
            const int kb = cid >> 5, nc = cid & 31;
            cp_async16(sBu0 + (uint32_t)(kb * BPITCH + nc * 4) * 4u,
                       Bg + (size_t)kb * N3 + nc * 4);
        }
        cp_commit();
    }

    #pragma unroll 1
    for (int kt = 0; kt < 32; kt++) {
        const int s = kt & 1;
        const bool more = (kt + 1 < 32);
        if (more) {
            const int ns = s ^ 1;
            const int k0 = (kt + 1) * BK;
            const uint32_t dA = sAu0 + (uint32_t)(ns * BM * APITCH + tid * APITCH) * 4u;
            const float* srcA = Ag + (size_t)tid * DIM + k0;
            #pragma unroll
            for (int kc = 0; kc < 4; kc++) cp_async16(dA + kc * 16u, srcA + kc * 4);
            const uint32_t dB = sBu0 + (uint32_t)(ns * BK * BPITCH) * 4u;
            #pragma unroll
            for (int i = 0; i < 4; i++) {
                const int cid = i * 128 + tid;
                const int kb = cid >> 5, nc = cid & 31;
                cp_async16(dB + (uint32_t)(kb * BPITCH + nc * 4) * 4u,
                           Bg + (size_t)(k0 + kb) * N3 + nc * 4);
            }
            cp_commit();
            cp_wait<1>();
        } else {
            cp_wait<0>();
        }
        __syncthreads();

        const float* As = &sA[s][0];
        const float* Bs = &sB[s][0];
        #pragma unroll
        for (int kk = 0; kk < 16; kk += 8) {
            uint32_t a[4][4], b[8][2];
            #pragma unroll
            for (int mi = 0; mi < 4; mi++) {
                const int m = wm + mi * 16 + gid;
                a[mi][0] = __float_as_uint(As[m * APITCH + kk + tig]);
                a[mi][1] = __float_as_uint(As[(m + 8) * APITCH + kk + tig]);
                a[mi][2] = __float_as_uint(As[m * APITCH + kk + tig + 4]);
                a[mi][3] = __float_as_uint(As[(m + 8) * APITCH + kk + tig + 4]);
            }
            #pragma unroll
            for (int ni = 0; ni < 8; ni++) {
                const int n = wn + ni * 8 + gid;
                b[ni][0] = __float_as_uint(Bs[(kk + tig) * BPITCH + n]);
                b[ni][1] = __float_as_uint(Bs[(kk + tig + 4) * BPITCH + n]);
            }
            #pragma unroll
            for (int mi = 0; mi < 4; mi++)
                #pragma unroll
                for (int ni = 0; ni < 8; ni++)
                    mma_tf32(acc[mi][ni], a[mi], b[ni]);
        }
        __syncthreads();   // stage s gets overwritten two iterations later by prefetch
    }

    // epilogue
    #pragma unroll
    for (int mi = 0; mi < 4; mi++) {
        #pragma unroll
        for (int ni = 0; ni < 8; ni++) {
            const int row = m0 + wm + mi * 16 + gid;
            const int col = n0 + wn + ni * 8 + tig * 2;
            *(float2*)&C[(size_t)row * N3 + col] =
                make_float2(acc[mi][ni][0], acc[mi][ni][1]);
            *(float2*)&C[(size_t)(row + 8) * N3 + col] =
                make_float2(acc[mi][ni][2], acc[mi][ni][3]);
        }
    }
}

// ---------------------------------------------------------------------------
// Fused T projection: one pass over X computes all 7 nodes' gates.
// W_T cached in smem (transposed for conflict-free reads).
// ---------------------------------------------------------------------------
__global__ __launch_bounds__(128) void tproj_kernel(const float* __restrict__ X,
                                                    const float* __restrict__ WT,
                                                    const float* __restrict__ bT) {
    __shared__ float swt[2][NODES][DIM];   // 28 KB
    const int tid = threadIdx.x;
    for (int idx = tid; idx < NODES * DIM * 2; idx += 128) {
        const int node = idx / (DIM * 2);
        const int r = idx - node * DIM * 2;
        const int k = r >> 1;
        const int j = r & 1;
        swt[j][node][k] = WT[idx];
    }
    __syncthreads();

    const int w = tid >> 5;
    const int lane = tid & 31;
    const int m0 = blockIdx.x * 128 + w * 32;

    float bt[NODES][2];
    #pragma unroll
    for (int n = 0; n < NODES; n++) {
        bt[n][0] = bT[n * 2 + 0];
        bt[n][1] = bT[n * 2 + 1];
    }

    for (int r = 0; r < 32; r++) {
        const int m = m0 + r;
        const float* xr = X + (size_t)m * DIM;
        float s[NODES][2];
        #pragma unroll
        for (int n = 0; n < NODES; n++) s[n][0] = s[n][1] = 0.0f;
        #pragma unroll 4
        for (int k = lane; k < DIM; k += 32) {
            const float x = xr[k];
            #pragma unroll
            for (int n = 0; n < NODES; n++) {
                s[n][0] = fmaf(x, swt[0][n][k], s[n][0]);
                s[n][1] = fmaf(x, swt[1][n][k], s[n][1]);
            }
        }
        #pragma unroll
        for (int n = 0; n < NODES; n++)
            #pragma unroll
            for (int j = 0; j < 2; j++)
                #pragma unroll
                for (int o = 16; o > 0; o >>= 1)
                    s[n][j] += __shfl_down_sync(0xFFFFFFFFu, s[n][j], o);
        if (lane == 0) {
            #pragma unroll
            for (int n = 0; n < NODES; n++) {
                const size_t t = ((size_t)n * MROWS + m) * 2;
                g_T[t + 0] = sigmoidf(s[n][0] + bt[n][0]);
                g_T[t + 1] = sigmoidf(s[n][1] + bt[n][1]);
            }
        }
    }
}

// ---------------------------------------------------------------------------
// Chunked scan, pass A: per (node, chunk, lane) affine summary (A, B)
// ---------------------------------------------------------------------------
template<bool INTERNAL>
__global__ __launch_bounds__(128) void scanA_kernel(int first_node) {
    const int node  = first_node + blockIdx.z;
    const int chunk = blockIdx.y;
    const int lane  = blockIdx.x * 128 + threadIdx.x;
    const int b = lane >> 9;
    const int h = lane & 511;

    const float* Vn = g_V + (size_t)node * MROWS * N3;
    const float* Tn = g_T + (size_t)node * MROWS * 2;
    const float* HF = g_H + (size_t)(2 * node) * MROWS * HID;

    float A = 1.0f, Bc = 0.0f;
    const int s0 = chunk * CHLEN;
    #pragma unroll 4
    for (int si = 0; si < CHLEN; si++) {
        const int m = (s0 + si) * BATCH + b;
        const size_t vi = (size_t)m * N3 + h;
        float z = __ldg(Vn + vi);
        float f = __ldg(Vn + vi + HID);
        if (INTERNAL) {
            const float t1 = __ldg(Tn + (size_t)m * 2);
            const float hF = __ldg(HF + (size_t)m * HID + h);
            f = hF * t1 + (1.0f - t1) * f;
        }
        z = fmaxf(z, 0.0f);
        f = sigmoidf(f);
        const float a = 1.0f - f;
        A *= a;
        Bc = fmaf(a, Bc, f * z);
    }
    const size_t idx = ((size_t)node * NCHUNK + chunk) * LANES + lane;
    g_A[idx] = A;
    g_Bc[idx] = Bc;
}

// Pass mid: load all summaries first (full MLP), then chain.
__global__ __launch_bounds__(128) void scanMid_kernel(int first_node) {
    const int node = first_node + blockIdx.y;
    const int lane = blockIdx.x * 128 + threadIdx.x;
    float av[NCHUNK], bv[NCHUNK];
    const size_t base = (size_t)node * NCHUNK * LANES + lane;
    #pragma unroll
    for (int j = 0; j < NCHUNK; j++) {
        av[j] = g_A[base + (size_t)j * LANES];
        bv[j] = g_Bc[base + (size_t)j * LANES];
    }
    float c = 0.0f;
    #pragma unroll
    for (int j = 0; j < NCHUNK; j++) {
        g_Cin[base + (size_t)j * LANES] = c;
        c = fmaf(av[j], c, bv[j]);
    }
}

template<bool INTERNAL, bool ROOT>
__global__ __launch_bounds__(128) void scanB_kernel(int first_node,
                                                    const float* __restrict__ X,
                                                    float* __restrict__ out) {
    const int node  = first_node + blockIdx.z;
    const int chunk = blockIdx.y;
    const int lane  = blockIdx.x * 128 + threadIdx.x;
    const int b = lane >> 9;
    const int h = lane & 511;

    const float* Vn = g_V + (size_t)node * MROWS * N3;
    const float* Tn = g_T + (size_t)node * MROWS * 2;
    const float* HF = g_H + (size_t)(2 * node) * MROWS * HID;
    const float* HO = g_H + (size_t)(2 * node + 1) * MROWS * HID;
    float* hout = ROOT ? out : (g_H + (size_t)(node - 1) * MROWS * HID);

    float c = g_Cin[((size_t)node * NCHUNK + chunk) * LANES + lane];
    float cm = -3.4e38f;
    const int s0 = chunk * CHLEN;
    #pragma unroll 4
    for (int si = 0; si < CHLEN; si++) {
        const int m = (s0 + si) * BATCH + b;
        const size_t vi = (size_t)m * N3 + h;
        float z = __ldg(Vn + vi);
        float f = __ldg(Vn + vi + HID);
        float o = __ldg(Vn + vi + 2 * HID);
        if (INTERNAL) {
            const float2 t = *(const float2*)(Tn + (size_t)m * 2);
            const float hF = __ldg(HF + (size_t)m * HID + h);
            const float hO = __ldg(HO + (size_t)m * HID + h);
            f = hF * t.x + (1.0f - t.x) * f;
            o = hO * t.y + (1.0f - t.y) * o;
        }
        z = fmaxf(z, 0.0f);
        f = sigmoidf(f);
        c = fmaf(f, z, (1.0f - f) * c);
        const float ho = c * sigmoidf(o);
        if (ROOT) cm = fmaxf(cm, ho);
        hout[(size_t)m * HID + h] = ho + __ldg(X + (size_t)m * DIM + h);
    }
    if (ROOT) g_CM[(size_t)chunk * LANES + lane] = cm;
}

__global__ __launch_bounds__(128) void cmax_kernel(float* __restrict__ cmax_out) {
    const int lane = blockIdx.x * 128 + threadIdx.x;
    float cm = -3.4e38f;
    #pragma unroll
    for (int j = 0; j < NCHUNK; j++)
        cm = fmaxf(cm, g_CM[(size_t)j * LANES + lane]);
    cmax_out[lane] = cm;
}

// ---------------------------------------------------------------------------
extern "C" void kernel_launch(void* const* d_in, const int* in_sizes, int n_in,
                              void* d_out, int out_size) {
    const float* X  = (const float*)d_in[0];
    const float* Wp = (const float*)d_in[1];
    const float* WT = (const float*)d_in[2];
    const float* bT = (const float*)d_in[3];
    float* out = (float*)d_out;
    (void)in_sizes; (void)n_in;

    gemm_tf32_kernel<<<dim3(N3 / BN, MROWS / BM, NODES), 128>>>(X, Wp);
    tproj_kernel<<<MROWS / 128, 128>>>(X, WT, bT);

    const dim3 blk(128);
    {   // leaves 3..6
        dim3 g(LANES / 128, NCHUNK, 4);
        scanA_kernel<false><<<g, blk>>>(3);
        scanMid_kernel<<<dim3(LANES / 128, 4), blk>>>(3);
        scanB_kernel<false, false><<<g, blk>>>(3, X, out);
    }
    {   // nodes 1,2
        dim3 g(LANES / 128, NCHUNK, 2);
        scanA_kernel<true><<<g, blk>>>(1);
        scanMid_kernel<<<dim3(LANES / 128, 2), blk>>>(1);
        scanB_kernel<true, false><<<g, blk>>>(1, X, out);
    }
    {   // root node 0
        dim3 g(LANES / 128, NCHUNK, 1);
        scanA_kernel<true><<<g, blk>>>(0);
        scanMid_kernel<<<dim3(LANES / 128, 1), blk>>>(0);
        scanB_kernel<true, true><<<g, blk>>>(0, X, out);
    }
    if (out_size >= MROWS * HID + LANES)
        cmax_kernel<<<LANES / 128, blk>>>(out + (size_t)MROWS * HID);
}